// round 7
// baseline (speedup 1.0000x reference)
#include <cuda_runtime.h>
#include <cuda_bf16.h>
#include <cstdint>

#define NPITCH 226
#define NFFT   1536
#define HOP    384
#define TFRM   497
#define XLEN   192000
#define NFRAMES (2 * TFRM)
#define NT     384
#define FPB    7      // frames per block
#define GRID   148    // == #SMs: one CTA per SM, deterministic wave-1 placement

// Persistent-style: block i handles the 7 consecutive frames [7i, 7i+7).
// Per frame: out[b,t,l] = win[l] * (0.25*(x[384t+l-d]+x[384t+l+d]) + 0.5*x[384t+l])
// with d = 767 - 3*pitch (rows 0..224) or a unit delta (row 225) — exact
// structure of the reference's comb bank, so conv_w is never read.
// l = tid + 384u (u=0..3): lane-stride-1 accesses; the 384-step in l is a
// pi/2 Hann phase step, so one sincospif gives all 4 window values, computed
// ONCE for all 7 frames. All 7 pitch loads issue up front (independent).
__global__ __launch_bounds__(NT)
void comb_fused_kernel(const float* __restrict__ x,
                       const int*   __restrict__ pitch,
                       float*       __restrict__ out) {
    const int tid = threadIdx.x;
    const int fr0 = blockIdx.x * FPB;

    // Window once per thread (shared by all frames).
    float sn, cs;
    sincospif((float)tid * (1.0f / 768.0f), &sn, &cs);
    const float win[4] = {0.5f - 0.5f * cs, 0.5f + 0.5f * sn,
                          0.5f + 0.5f * cs, 0.5f - 0.5f * sn};

    // Prefetch all pitches (independent loads, clamped for masked tail).
    int pv[FPB];
#pragma unroll
    for (int i = 0; i < FPB; i++) {
        int fr = fr0 + i;
        pv[i] = __ldg(pitch + ((fr < NFRAMES) ? fr : (NFRAMES - 1)));
    }

#pragma unroll 2
    for (int i = 0; i < FPB; i++) {
        const int fr = fr0 + i;
        if (fr >= NFRAMES) continue;

        const int b = (fr >= TFRM) ? 1 : 0;
        const int t = fr - b * TFRM;

        const int   f  = pv[i];
        const int   d  = (f == NPITCH - 1) ? 0 : (767 - 3 * f);
        const float wc = (f == NPITCH - 1) ? 1.0f : 0.5f;
        const float ws = (f == NPITCH - 1) ? 0.0f : 0.25f;

        const float* xb = x + (size_t)b * XLEN;
        const int    c0 = t * HOP + tid;          // = 384t + l at u=0
        float*       ob = out + (size_t)fr * NFFT;

        float acc[4];
        if (t >= 2 && t <= 494) {
            // Interior: every tap index lies in [0, XLEN).
            const float* pc = xb + c0;
            float vc[4], vl[4], vr[4];
#pragma unroll
            for (int u = 0; u < 4; u++) vc[u] = __ldg(pc + u * NT);
#pragma unroll
            for (int u = 0; u < 4; u++) {
                vl[u] = __ldg(pc + u * NT - d);
                vr[u] = __ldg(pc + u * NT + d);
            }
#pragma unroll
            for (int u = 0; u < 4; u++)
                acc[u] = fmaf(ws, vl[u] + vr[u], wc * vc[u]);
        } else {
#pragma unroll
            for (int u = 0; u < 4; u++) {
                const int ic = c0 + u * NT;
                const int il = ic - d, ir = ic + d;
                const float xc = ((unsigned)ic < (unsigned)XLEN) ? __ldg(xb + ic) : 0.0f;
                const float xl = ((unsigned)il < (unsigned)XLEN) ? __ldg(xb + il) : 0.0f;
                const float xr = ((unsigned)ir < (unsigned)XLEN) ? __ldg(xb + ir) : 0.0f;
                acc[u] = fmaf(ws, xl + xr, wc * xc);
            }
        }

#pragma unroll
        for (int u = 0; u < 4; u++)
            ob[tid + u * NT] = acc[u] * win[u];
    }
}

extern "C" void kernel_launch(void* const* d_in, const int* in_sizes, int n_in,
                              void* d_out, int out_size) {
    const float* x     = (const float*)d_in[0];   // (2, 192000) f32
    const int*   pitch = (const int*)  d_in[1];   // (2, 497)    i32
    float*       out   = (float*)d_out;           // (2,497,1536,1) f32

    comb_fused_kernel<<<GRID, NT>>>(x, pitch, out);
}

// round 8
// speedup vs baseline: 1.3204x; 1.3204x over previous
#include <cuda_runtime.h>
#include <cuda_bf16.h>
#include <cstdint>

#define NPITCH 226
#define NFFT   1536
#define HOP    384
#define TFRM   497
#define XLEN   192000
#define NFRAMES (2 * TFRM)
#define NT     128
#define SPAN   3072   // x-span per frame: [384t-768, 384t+2304)

// One block per (b,t) frame, 128 threads, 12 outputs/thread (l = tid + 128u).
//
// Stage the frame's x-span into smem first (pitch-independent, coalesced
// float4), then compute all taps from smem:
//   out[b,t,l] = win[l] * (0.25*(s[i-d]+s[i+d]) + 0.5*s[i]), i = 768+l,
//   d = 767 - 3*pitch (rows 0..224) or unit delta (row 225) — the exact
//   structure of the reference comb bank, so conv_w is never read.
// Window: theta = pi*l/768, l = tid+128u => +u*pi/6 steps, one sincospif +
// exact angle-addition constants.
__global__ __launch_bounds__(NT)
void comb_fused_kernel(const float* __restrict__ x,
                       const int*   __restrict__ pitch,
                       float*       __restrict__ out) {
    __shared__ float s[SPAN];

    const int tid   = threadIdx.x;
    const int frame = blockIdx.x;             // b*TFRM + t
    const int b     = (frame >= TFRM) ? 1 : 0;
    const int t     = frame - b * TFRM;

    const int f = __ldg(pitch + frame);       // issue early; only gates LDS

    const float* xb = x + (size_t)b * XLEN;
    const int    g0 = t * HOP - 768;          // first staged sample index

    if (t >= 2 && t <= 494) {
        // Interior: whole span in bounds; g0 % 4 == 0 -> aligned float4.
        const float4* src = reinterpret_cast<const float4*>(xb + g0);
        float4*       dst = reinterpret_cast<float4*>(s);
#pragma unroll
        for (int i = 0; i < 6; i++)
            dst[tid + i * NT] = __ldg(src + tid + i * NT);
    } else {
        // Edge frames (8 of 994): scalar bounds-checked staging.
#pragma unroll
        for (int i = 0; i < 24; i++) {
            const int j = tid + i * NT;
            const int g = g0 + j;
            s[j] = ((unsigned)g < (unsigned)XLEN) ? __ldg(xb + g) : 0.0f;
        }
    }

    const int   d  = (f == NPITCH - 1) ? 0 : (767 - 3 * f);
    const float wc = (f == NPITCH - 1) ? 1.0f : 0.5f;
    const float ws = (f == NPITCH - 1) ? 0.0f : 0.25f;

    // Window: win[u] = 0.5 - 0.5*cos(pi*tid/768 + u*pi/6)
    float sn, cs;
    sincospif((float)tid * (1.0f / 768.0f), &sn, &cs);
    const float R3H = 0.86602540378443864676f;  // sqrt(3)/2
    const float Cu[12] = { 1.0f,  R3H,  0.5f, 0.0f, -0.5f, -R3H,
                          -1.0f, -R3H, -0.5f, 0.0f,  0.5f,  R3H};
    const float Su[12] = { 0.0f, 0.5f,  R3H, 1.0f,  R3H,  0.5f,
                           0.0f,-0.5f, -R3H,-1.0f, -R3H, -0.5f};

    __syncthreads();

    float* ob = out + (size_t)frame * NFFT;
    const int i0 = 768 + tid;                  // smem index of l = tid

#pragma unroll
    for (int u = 0; u < 12; u++) {
        const int   i   = i0 + u * NT;
        const float vc  = s[i];
        const float vlr = s[i - d] + s[i + d];
        const float win = 0.5f - 0.5f * (cs * Cu[u] - sn * Su[u]);
        ob[tid + u * NT] = fmaf(ws, vlr, wc * vc) * win;
    }
}

extern "C" void kernel_launch(void* const* d_in, const int* in_sizes, int n_in,
                              void* d_out, int out_size) {
    const float* x     = (const float*)d_in[0];   // (2, 192000) f32
    const int*   pitch = (const int*)  d_in[1];   // (2, 497)    i32
    float*       out   = (float*)d_out;           // (2,497,1536,1) f32

    comb_fused_kernel<<<NFRAMES, NT>>>(x, pitch, out);
}